// round 8
// baseline (speedup 1.0000x reference)
#include <cuda_runtime.h>
#include <cstdint>

// GaussianRP: x (8,16,32,1024) f32, log_sigma scalar f32
// out (8,16,1024,1024) f32:
//   rp[b,c,t,s] = exp(-max(|x_t|^2+|x_s|^2-2<x_t,x_s>, 0) / (2 sigma^2))
//
// Round 7: 3xTF32 mma.sync Gram with PRE-PACKED fragments. A one-time pack
// kernel splits x into tf32 hi/lo and writes them to global arrays already in
// m16n8k8 fragment order (A-layout and B-layout). The Gram kernel has no
// smem, no __syncthreads, no conversion math: coalesced lane-linear LDG of
// fragments -> MMA chain -> exp epilogue. 128x128 tile, 512 thr, warp=32x32.
// Symmetric tile pairs (36/64), dual store.

#define NDIM  32
#define NT    1024
#define NBC   128

#define TILE  128
#define NTILE (NT / TILE)                  // 8
#define NPAIR (NTILE * (NTILE + 1) / 2)    // 36

#define TWORDS 4096                        // fragment words per (bc,tile)
#define FR_TOT (NBC * NTILE * TWORDS)      // 4,194,304 per array

__device__ float g_sqnorm[NBC * NT];
__device__ float g_scale;   // 1/(2 sigma^2)

__device__ float g_Ahi[FR_TOT];
__device__ float g_Alo[FR_TOT];
__device__ float g_Bhi[FR_TOT];
__device__ float g_Blo[FR_TOT];

__device__ __forceinline__ uint32_t f2tf32(float v) {
    uint32_t r;
    asm("cvt.rna.tf32.f32 %0, %1;" : "=r"(r) : "f"(v));
    return r;
}

__global__ __launch_bounds__(256)
void norms_kernel(const float* __restrict__ x,
                  const float* __restrict__ log_sigma) {
    int idx = blockIdx.x * blockDim.x + threadIdx.x;
    if (idx == 0) g_scale = 0.5f * __expf(-2.f * log_sigma[0]);
    if (idx >= NBC * NT) return;
    int bc = idx >> 10;
    int t  = idx & (NT - 1);
    const float* p = x + (size_t)bc * NDIM * NT + t;
    float s = 0.f;
#pragma unroll
    for (int d = 0; d < NDIM; ++d) {
        float v = p[d * NT];
        s = fmaf(v, v, s);
    }
    g_sqnorm[idx] = s;
}

// One thread per destination fragment word (A range then B range).
// A word  w: idxA=w&3, lane=(w>>2)&31, ks=(w>>7)&3, ms=(w>>9)&7,
//            tile=(w>>12)&7, bc=w>>15
//   -> tloc = ms*16 + ((idxA>>1)&1)*8 + (lane>>2)
//      k    = ks*8  + (idxA&1)*4      + (lane&3)
// B word  w: idxB=w&1, lane=(w>>1)&31, ks=(w>>6)&3, nb=(w>>8)&15,
//            tile=(w>>12)&7, bc=w>>15
//   -> sloc = nb*8 + (lane>>2)
//      k    = ks*8 + idxB*4 + (lane&3)
__global__ __launch_bounds__(256)
void pack_kernel(const float* __restrict__ x) {
    int idx = blockIdx.x * blockDim.x + threadIdx.x;
    if (idx < FR_TOT) {
        int w    = idx;
        int idxA = w & 3;
        int lane = (w >> 2) & 31;
        int ks   = (w >> 7) & 3;
        int ms   = (w >> 9) & 7;
        int tile = (w >> 12) & 7;
        int bc   = w >> 15;
        int tl   = ms * 16 + ((idxA >> 1) & 1) * 8 + (lane >> 2);
        int k    = ks * 8 + (idxA & 1) * 4 + (lane & 3);
        float v  = x[(size_t)bc * NDIM * NT + k * NT + tile * TILE + tl];
        float hf = __uint_as_float(f2tf32(v));
        g_Ahi[w] = hf;
        g_Alo[w] = __uint_as_float(f2tf32(v - hf));
    } else if (idx < 2 * FR_TOT) {
        int w    = idx - FR_TOT;
        int idxB = w & 1;
        int lane = (w >> 1) & 31;
        int ks   = (w >> 6) & 3;
        int nb   = (w >> 8) & 15;
        int tile = (w >> 12) & 7;
        int bc   = w >> 15;
        int sl   = nb * 8 + (lane >> 2);
        int k    = ks * 8 + idxB * 4 + (lane & 3);
        float v  = x[(size_t)bc * NDIM * NT + k * NT + tile * TILE + sl];
        float hf = __uint_as_float(f2tf32(v));
        g_Bhi[w] = hf;
        g_Blo[w] = __uint_as_float(f2tf32(v - hf));
    }
}

__device__ __forceinline__ void mma_tf32(float d[4],
                                         uint32_t a0, uint32_t a1,
                                         uint32_t a2, uint32_t a3,
                                         uint32_t b0, uint32_t b1) {
    asm volatile(
        "mma.sync.aligned.m16n8k8.row.col.f32.tf32.tf32.f32 "
        "{%0,%1,%2,%3}, {%4,%5,%6,%7}, {%8,%9}, {%0,%1,%2,%3};"
        : "+f"(d[0]), "+f"(d[1]), "+f"(d[2]), "+f"(d[3])
        : "r"(a0), "r"(a1), "r"(a2), "r"(a3), "r"(b0), "r"(b1));
}

__global__ __launch_bounds__(512)
void gaussian_rp_mma(float* __restrict__ out) {
    const int bc = blockIdx.x;
    const int p  = blockIdx.y;

    int ss = 0;
#pragma unroll
    for (int c = 1; c < NTILE; ++c)
        ss += (p >= c * (c + 1) / 2) ? 1 : 0;
    const int ts = p - ss * (ss + 1) / 2;
    const int t0 = ts * TILE;
    const int s0 = ss * TILE;

    const int tid  = threadIdx.x;
    const int lane = tid & 31;
    const int wid  = tid >> 5;        // 0..15
    const int wm   = wid & 3;          // t-group (rows wm*32..+31)
    const int wn   = wid >> 2;         // s-group (cols wn*32..+31)
    const int g    = lane >> 2;
    const int tig  = lane & 3;

    const uint32_t* Ahi = (const uint32_t*)g_Ahi + (size_t)(bc * NTILE + ts) * TWORDS;
    const uint32_t* Alo = (const uint32_t*)g_Alo + (size_t)(bc * NTILE + ts) * TWORDS;
    const uint32_t* Bhi = (const uint32_t*)g_Bhi + (size_t)(bc * NTILE + ss) * TWORDS;
    const uint32_t* Blo = (const uint32_t*)g_Blo + (size_t)(bc * NTILE + ss) * TWORDS;

    float acc[2][4][4];
#pragma unroll
    for (int i = 0; i < 2; ++i)
#pragma unroll
        for (int j = 0; j < 4; ++j)
#pragma unroll
            for (int q = 0; q < 4; ++q) acc[i][j][q] = 0.f;

#pragma unroll
    for (int kk = 0; kk < 4; ++kk) {
        uint4 fh[2], fl[2];
#pragma unroll
        for (int msi = 0; msi < 2; ++msi) {
            int off = (((wm * 2 + msi) * 4 + kk) * 32 + lane) * 4;
            fh[msi] = *(const uint4*)(Ahi + off);
            fl[msi] = *(const uint4*)(Alo + off);
        }
#pragma unroll
        for (int nbl = 0; nbl < 4; ++nbl) {
            int boff = (((wn * 4 + nbl) * 4 + kk) * 32 + lane) * 2;
            uint2 bh = *(const uint2*)(Bhi + boff);
            uint2 bl = *(const uint2*)(Blo + boff);
#pragma unroll
            for (int msi = 0; msi < 2; ++msi) {
                // stored order [a0,a2,a1,a3] -> operands (a0,a1,a2,a3)
                mma_tf32(acc[msi][nbl], fh[msi].x, fh[msi].z, fh[msi].y, fh[msi].w, bh.x, bh.y); // hi*hi
                mma_tf32(acc[msi][nbl], fl[msi].x, fl[msi].z, fl[msi].y, fl[msi].w, bh.x, bh.y); // lo*hi
                mma_tf32(acc[msi][nbl], fh[msi].x, fh[msi].z, fh[msi].y, fh[msi].w, bl.x, bl.y); // hi*lo
            }
        }
    }

    // ---- epilogue: d2 -> exp -> dual store ----
    const float scale  = g_scale;
    const float scale2 = 2.f * scale;
    const float* sq = &g_sqnorm[bc * NT];

    float snt[2][2], sns[4][2];
#pragma unroll
    for (int msi = 0; msi < 2; ++msi) {
        int tl = wm * 32 + msi * 16 + g;
        snt[msi][0] = scale * sq[t0 + tl];
        snt[msi][1] = scale * sq[t0 + tl + 8];
    }
#pragma unroll
    for (int nbl = 0; nbl < 4; ++nbl) {
        int sl = wn * 32 + nbl * 8 + 2 * tig;
        sns[nbl][0] = scale * sq[s0 + sl];
        sns[nbl][1] = scale * sq[s0 + sl + 1];
    }

    float* ob = out + (size_t)bc * NT * NT;
    const bool offdiag = (ts != ss);

#pragma unroll
    for (int msi = 0; msi < 2; ++msi) {
#pragma unroll
        for (int nbl = 0; nbl < 4; ++nbl) {
            float* d = acc[msi][nbl];
            float r0 = __expf(fminf(fmaf(scale2, d[0], -(snt[msi][0] + sns[nbl][0])), 0.f));
            float r1 = __expf(fminf(fmaf(scale2, d[1], -(snt[msi][0] + sns[nbl][1])), 0.f));
            float r2 = __expf(fminf(fmaf(scale2, d[2], -(snt[msi][1] + sns[nbl][0])), 0.f));
            float r3 = __expf(fminf(fmaf(scale2, d[3], -(snt[msi][1] + sns[nbl][1])), 0.f));

            int tl = wm * 32 + msi * 16 + g;
            int sl = wn * 32 + nbl * 8 + 2 * tig;

            *(float2*)(ob + (size_t)(t0 + tl) * NT + s0 + sl)     = make_float2(r0, r1);
            *(float2*)(ob + (size_t)(t0 + tl + 8) * NT + s0 + sl) = make_float2(r2, r3);

            if (offdiag) {
                ob[(size_t)(s0 + sl)     * NT + t0 + tl]     = r0;
                ob[(size_t)(s0 + sl + 1) * NT + t0 + tl]     = r1;
                ob[(size_t)(s0 + sl)     * NT + t0 + tl + 8] = r2;
                ob[(size_t)(s0 + sl + 1) * NT + t0 + tl + 8] = r3;
            }
        }
    }
}

extern "C" void kernel_launch(void* const* d_in, const int* in_sizes, int n_in,
                              void* d_out, int out_size) {
    const float* x  = (const float*)d_in[0];
    const float* ls = (const float*)d_in[1];
    float* out      = (float*)d_out;

    norms_kernel<<<(NBC * NT + 255) / 256, 256>>>(x, ls);
    pack_kernel<<<(2 * FR_TOT + 255) / 256, 256>>>(x);

    dim3 grid(NBC, NPAIR);
    gaussian_rp_mma<<<grid, 512>>>(out);
}

// round 10
// speedup vs baseline: 1.5324x; 1.5324x over previous
#include <cuda_runtime.h>
#include <cstdint>

// GaussianRP: x (8,16,32,1024) f32, log_sigma scalar f32
// out (8,16,1024,1024) f32:
//   rp[b,c,t,s] = exp(-max(|x_t|^2+|x_s|^2-2<x_t,x_s>, 0) / (2 sigma^2))
//
// Round 9 (= R8 resubmit; R8 never ran due to infra): 3xTF32 mma.sync Gram,
// restructured for CTA co-residency. 64x64 tile, 256 threads,
// launch_bounds(256,3) -> 3 CTAs/SM so load/MMA/exp-store phases of
// different blocks overlap. Fragments pre-packed in global memory in
// m16n8k8 order (one-time pack kernel); grid is (pair, bc) with pair
// fastest so the per-bc fragment set stays L2-resident. Symmetric tile
// pairs (136/256), dual store.

#define NDIM  32
#define NT    1024
#define NBC   128

#define TILE  64
#define NTILE (NT / TILE)                  // 16
#define NPAIR (NTILE * (NTILE + 1) / 2)    // 136

#define TWORDS 2048                        // fragment words per (bc,tile)
#define FR_TOT (NBC * NTILE * TWORDS)      // 4,194,304 per array

__device__ float g_sqnorm[NBC * NT];
__device__ float g_scale;   // 1/(2 sigma^2)

__device__ float g_Ahi[FR_TOT];
__device__ float g_Alo[FR_TOT];
__device__ float g_Bhi[FR_TOT];
__device__ float g_Blo[FR_TOT];

__device__ __forceinline__ uint32_t f2tf32(float v) {
    uint32_t r;
    asm("cvt.rna.tf32.f32 %0, %1;" : "=r"(r) : "f"(v));
    return r;
}

__global__ __launch_bounds__(256)
void norms_kernel(const float* __restrict__ x,
                  const float* __restrict__ log_sigma) {
    int idx = blockIdx.x * blockDim.x + threadIdx.x;
    if (idx == 0) g_scale = 0.5f * __expf(-2.f * log_sigma[0]);
    if (idx >= NBC * NT) return;
    int bc = idx >> 10;
    int t  = idx & (NT - 1);
    const float* p = x + (size_t)bc * NDIM * NT + t;
    float s = 0.f;
#pragma unroll
    for (int d = 0; d < NDIM; ++d) {
        float v = p[d * NT];
        s = fmaf(v, v, s);
    }
    g_sqnorm[idx] = s;
}

// One thread per destination fragment word (A range then B range).
// Per-(bc) A block = 16 tiles * 2048 words = 2^15.
// A word w: idxA=w&3, lane=(w>>2)&31, ks=(w>>7)&3, ms=(w>>9)&3,
//           tile=(w>>11)&15, bc=w>>15
//   tl = ms*16 + ((idxA>>1)&1)*8 + (lane>>2);  k = ks*8 + (idxA&1)*4 + (lane&3)
// B word w: idxB=w&1, lane=(w>>1)&31, ks=(w>>6)&3, nb=(w>>8)&7,
//           tile=(w>>11)&15, bc=w>>15
//   sl = nb*8 + (lane>>2);                     k = ks*8 + idxB*4 + (lane&3)
__global__ __launch_bounds__(256)
void pack_kernel(const float* __restrict__ x) {
    int idx = blockIdx.x * blockDim.x + threadIdx.x;
    if (idx < FR_TOT) {
        int w    = idx;
        int idxA = w & 3;
        int lane = (w >> 2) & 31;
        int ks   = (w >> 7) & 3;
        int ms   = (w >> 9) & 3;
        int tile = (w >> 11) & 15;
        int bc   = w >> 15;
        int tl   = ms * 16 + ((idxA >> 1) & 1) * 8 + (lane >> 2);
        int k    = ks * 8 + (idxA & 1) * 4 + (lane & 3);
        float v  = x[(size_t)bc * NDIM * NT + k * NT + tile * TILE + tl];
        float hf = __uint_as_float(f2tf32(v));
        g_Ahi[w] = hf;
        g_Alo[w] = __uint_as_float(f2tf32(v - hf));
    } else if (idx < 2 * FR_TOT) {
        int w    = idx - FR_TOT;
        int idxB = w & 1;
        int lane = (w >> 1) & 31;
        int ks   = (w >> 6) & 3;
        int nb   = (w >> 8) & 7;
        int tile = (w >> 11) & 15;
        int bc   = w >> 15;
        int sl   = nb * 8 + (lane >> 2);
        int k    = ks * 8 + idxB * 4 + (lane & 3);
        float v  = x[(size_t)bc * NDIM * NT + k * NT + tile * TILE + sl];
        float hf = __uint_as_float(f2tf32(v));
        g_Bhi[w] = hf;
        g_Blo[w] = __uint_as_float(f2tf32(v - hf));
    }
}

__device__ __forceinline__ void mma_tf32(float d[4],
                                         uint32_t a0, uint32_t a1,
                                         uint32_t a2, uint32_t a3,
                                         uint32_t b0, uint32_t b1) {
    asm volatile(
        "mma.sync.aligned.m16n8k8.row.col.f32.tf32.tf32.f32 "
        "{%0,%1,%2,%3}, {%4,%5,%6,%7}, {%8,%9}, {%0,%1,%2,%3};"
        : "+f"(d[0]), "+f"(d[1]), "+f"(d[2]), "+f"(d[3])
        : "r"(a0), "r"(a1), "r"(a2), "r"(a3), "r"(b0), "r"(b1));
}

__global__ __launch_bounds__(256, 3)
void gaussian_rp_mma(float* __restrict__ out) {
    const int p  = blockIdx.x;        // pair fastest -> L2 locality per bc
    const int bc = blockIdx.y;

    int ss = 0;
#pragma unroll
    for (int c = 1; c < NTILE; ++c)
        ss += (p >= c * (c + 1) / 2) ? 1 : 0;
    const int ts = p - ss * (ss + 1) / 2;
    const int t0 = ts * TILE;
    const int s0 = ss * TILE;

    const int tid  = threadIdx.x;
    const int lane = tid & 31;
    const int wid  = tid >> 5;        // 0..7
    const int wm   = wid & 1;          // t half (32 rows)
    const int wn   = wid >> 1;         // s quarter (16 cols)
    const int g    = lane >> 2;
    const int tig  = lane & 3;

    const uint32_t* __restrict__ Ahi =
        (const uint32_t*)g_Ahi + (size_t)(bc * NTILE + ts) * TWORDS;
    const uint32_t* __restrict__ Alo =
        (const uint32_t*)g_Alo + (size_t)(bc * NTILE + ts) * TWORDS;
    const uint32_t* __restrict__ Bhi =
        (const uint32_t*)g_Bhi + (size_t)(bc * NTILE + ss) * TWORDS;
    const uint32_t* __restrict__ Blo =
        (const uint32_t*)g_Blo + (size_t)(bc * NTILE + ss) * TWORDS;

    float acc[2][2][4];
#pragma unroll
    for (int i = 0; i < 2; ++i)
#pragma unroll
        for (int j = 0; j < 2; ++j)
#pragma unroll
            for (int q = 0; q < 4; ++q) acc[i][j][q] = 0.f;

#pragma unroll
    for (int kk = 0; kk < 4; ++kk) {
        uint4 fh[2], fl[2];
#pragma unroll
        for (int msi = 0; msi < 2; ++msi) {
            int off = (((wm * 2 + msi) * 4 + kk) * 32 + lane) * 4;
            fh[msi] = *(const uint4*)(Ahi + off);
            fl[msi] = *(const uint4*)(Alo + off);
        }
#pragma unroll
        for (int nbl = 0; nbl < 2; ++nbl) {
            int boff = (((wn * 2 + nbl) * 4 + kk) * 32 + lane) * 2;
            uint2 bh = *(const uint2*)(Bhi + boff);
            uint2 bl = *(const uint2*)(Blo + boff);
#pragma unroll
            for (int msi = 0; msi < 2; ++msi) {
                // stored order [a0,a2,a1,a3] -> operands (a0,a1,a2,a3)
                mma_tf32(acc[msi][nbl], fh[msi].x, fh[msi].z, fh[msi].y, fh[msi].w, bh.x, bh.y); // hi*hi
                mma_tf32(acc[msi][nbl], fl[msi].x, fl[msi].z, fl[msi].y, fl[msi].w, bh.x, bh.y); // lo*hi
                mma_tf32(acc[msi][nbl], fh[msi].x, fh[msi].z, fh[msi].y, fh[msi].w, bl.x, bl.y); // hi*lo
            }
        }
    }

    // ---- epilogue: d2 -> exp -> dual store ----
    const float scale  = g_scale;
    const float scale2 = 2.f * scale;
    const float* sq = &g_sqnorm[bc * NT];

    float snt[2][2], sns[2][2];
#pragma unroll
    for (int msi = 0; msi < 2; ++msi) {
        int tl = wm * 32 + msi * 16 + g;
        snt[msi][0] = scale * sq[t0 + tl];
        snt[msi][1] = scale * sq[t0 + tl + 8];
    }
#pragma unroll
    for (int nbl = 0; nbl < 2; ++nbl) {
        int sl = wn * 16 + nbl * 8 + 2 * tig;
        sns[nbl][0] = scale * sq[s0 + sl];
        sns[nbl][1] = scale * sq[s0 + sl + 1];
    }

    float* ob = out + (size_t)bc * NT * NT;
    const bool offdiag = (ts != ss);

#pragma unroll
    for (int msi = 0; msi < 2; ++msi) {
#pragma unroll
        for (int nbl = 0; nbl < 2; ++nbl) {
            float* d = acc[msi][nbl];
            float r0 = __expf(fminf(fmaf(scale2, d[0], -(snt[msi][0] + sns[nbl][0])), 0.f));
            float r1 = __expf(fminf(fmaf(scale2, d[1], -(snt[msi][0] + sns[nbl][1])), 0.f));
            float r2 = __expf(fminf(fmaf(scale2, d[2], -(snt[msi][1] + sns[nbl][0])), 0.f));
            float r3 = __expf(fminf(fmaf(scale2, d[3], -(snt[msi][1] + sns[nbl][1])), 0.f));

            int tl = wm * 32 + msi * 16 + g;
            int sl = wn * 16 + nbl * 8 + 2 * tig;

            *(float2*)(ob + (size_t)(t0 + tl) * NT + s0 + sl)     = make_float2(r0, r1);
            *(float2*)(ob + (size_t)(t0 + tl + 8) * NT + s0 + sl) = make_float2(r2, r3);

            if (offdiag) {
                ob[(size_t)(s0 + sl)     * NT + t0 + tl]     = r0;
                ob[(size_t)(s0 + sl + 1) * NT + t0 + tl]     = r1;
                ob[(size_t)(s0 + sl)     * NT + t0 + tl + 8] = r2;
                ob[(size_t)(s0 + sl + 1) * NT + t0 + tl + 8] = r3;
            }
        }
    }
}

extern "C" void kernel_launch(void* const* d_in, const int* in_sizes, int n_in,
                              void* d_out, int out_size) {
    const float* x  = (const float*)d_in[0];
    const float* ls = (const float*)d_in[1];
    float* out      = (float*)d_out;

    norms_kernel<<<(NBC * NT + 255) / 256, 256>>>(x, ls);
    pack_kernel<<<(2 * FR_TOT + 255) / 256, 256>>>(x);

    dim3 grid(NPAIR, NBC);
    gaussian_rp_mma<<<grid, 256>>>(out);
}